// round 3
// baseline (speedup 1.0000x reference)
#include <cuda_runtime.h>
#include <math.h>
#include <stddef.h>

#define NB   2048
#define DL   256
#define XD   256
#define HID  1024
#define CIN  512
#define MAXIT 25

// ---------------- static device scratch (no allocs allowed) ----------------
__device__ float g_W1s[HID * CIN];
__device__ float g_W2s[DL * HID];
__device__ float g_u1[HID];
__device__ float g_v1[CIN];
__device__ float g_u2[DL];
__device__ float g_v2[HID];
__device__ float g_invsig[2];
__device__ float g_P[NB * HID];
__device__ float g_H[NB * HID];
__device__ float g_X0[NB * DL];
__device__ float g_Xs[23][NB * DL];   // X history slots t=3..25
__device__ float g_Fs[25][NB * DL];   // F history slots t=0..24

// ---------------- helpers ----------------
__device__ __forceinline__ float blk_reduce256(float v, float* sred, int tid) {
    #pragma unroll
    for (int o = 16; o; o >>= 1) v += __shfl_xor_sync(0xffffffffu, v, o);
    if ((tid & 31) == 0) sred[tid >> 5] = v;
    __syncthreads();
    if (tid < 32) {
        float x = (tid < 8) ? sred[tid] : 0.f;
        #pragma unroll
        for (int o = 4; o; o >>= 1) x += __shfl_xor_sync(0xffffffffu, x, o);
        if (tid == 0) sred[0] = x;
    }
    __syncthreads();
    float r = sred[0];
    __syncthreads();
    return r;
}

// ---------------- spectral norm power iteration ----------------
struct MvP { const float* W; int R; int C; const float* in; float* out; };

__global__ void init_uv() {
    int t = blockIdx.x * 256 + threadIdx.x;
    if (t < HID) g_u1[t] = 1.f;
    if (t < DL)  g_u2[t] = 1.f;
}

// out[C] = W^T normalize(in[R])   (output left UN-normalized; normalized on read)
__global__ void mv_vstep(MvP pa, MvP pb) {
    MvP p = blockIdx.y ? pb : pa;
    __shared__ float s_in[1024];
    __shared__ float sred[32];
    int tid = threadIdx.x;
    float ss = 0.f;
    for (int i = tid; i < p.R; i += 256) { float v = p.in[i]; s_in[i] = v; ss += v * v; }
    ss = blk_reduce256(ss, sred, tid);
    float inv = 1.f / (sqrtf(ss) + 1e-12f);
    int j = blockIdx.x * 256 + tid;
    if (j >= p.C) return;
    const float* Wc = p.W + j;
    float acc = 0.f;
    for (int i = 0; i < p.R; i++) acc += Wc[(size_t)i * p.C] * s_in[i];
    p.out[j] = acc * inv;
}

// out[R] = W * normalize(in[C])
__global__ void mv_ustep(MvP pa, MvP pb) {
    MvP p = blockIdx.y ? pb : pa;
    __shared__ float s_in[1024];
    __shared__ float sred[32];
    int tid = threadIdx.x;
    float ss = 0.f;
    for (int j = tid; j < p.C; j += 256) { float v = p.in[j]; s_in[j] = v; ss += v * v; }
    ss = blk_reduce256(ss, sred, tid);
    float inv = 1.f / (sqrtf(ss) + 1e-12f);
    int i = blockIdx.x * 256 + tid;
    if (i >= p.R) return;
    const float* Wr = p.W + (size_t)i * p.C;
    float acc = 0.f;
    for (int j = 0; j < p.C; j++) acc += Wr[j] * s_in[j];
    p.out[i] = acc * inv;
}

// sigma = ||v_raw||^2 / (||v_raw|| + 1e-12)   (== u . (W v_hat))
__global__ void sigma_k() {
    __shared__ float sred[32];
    const float* v = blockIdx.x ? g_v2 : g_v1;
    int n = blockIdx.x ? HID : CIN;
    int tid = threadIdx.x;
    float ss = 0.f;
    for (int i = tid; i < n; i += 256) { float x = v[i]; ss += x * x; }
    ss = blk_reduce256(ss, sred, tid);
    if (tid == 0) {
        float nr = sqrtf(ss);
        float sig = ss / (nr + 1e-12f);
        g_invsig[blockIdx.x] = 1.f / sig;
    }
}

__global__ void scale_k(const float* __restrict__ W1, const float* __restrict__ W2) {
    int i = blockIdx.x * 256 + threadIdx.x;
    const int n1 = HID * CIN;
    const int tot = n1 + DL * HID;
    if (i >= tot) return;
    if (i < n1) g_W1s[i] = W1[i] * g_invsig[0];
    else        g_W2s[i - n1] = W2[i - n1] * g_invsig[1];
}

// ---------------- GEMM (NT: both operands K-major) ----------------
// C[M,N] = act( A[M,K] @ B[N,K]^T + addend )
template<int BM, int BN, int BK, int TM, int TN, bool TANH, bool ADDMAT>
__global__ void __launch_bounds__((BM / TM) * (BN / TN))
gemm_nt(const float* __restrict__ A, int lda,
        const float* __restrict__ Bm, int ldb,
        float* __restrict__ C, int ldc, int K,
        const float* __restrict__ addv, const float* __restrict__ addm) {
    constexpr int THREADS = (BM / TM) * (BN / TN);
    constexpr int NX = BN / TN;
    __shared__ float As[BK][BM + 4];
    __shared__ float Bs[BK][BN + 4];
    int tid = threadIdx.x;
    int bm = blockIdx.y * BM, bn = blockIdx.x * BN;
    int tx = tid % NX, ty = tid / NX;
    float acc[TM][TN] = {};

    for (int k0 = 0; k0 < K; k0 += BK) {
        #pragma unroll
        for (int i = tid; i < BM * (BK / 4); i += THREADS) {
            int row = i / (BK / 4), c4 = i % (BK / 4);
            float4 v = *(const float4*)(A + (size_t)(bm + row) * lda + k0 + c4 * 4);
            As[c4 * 4 + 0][row] = v.x; As[c4 * 4 + 1][row] = v.y;
            As[c4 * 4 + 2][row] = v.z; As[c4 * 4 + 3][row] = v.w;
        }
        #pragma unroll
        for (int i = tid; i < BN * (BK / 4); i += THREADS) {
            int row = i / (BK / 4), c4 = i % (BK / 4);
            float4 v = *(const float4*)(Bm + (size_t)(bn + row) * ldb + k0 + c4 * 4);
            Bs[c4 * 4 + 0][row] = v.x; Bs[c4 * 4 + 1][row] = v.y;
            Bs[c4 * 4 + 2][row] = v.z; Bs[c4 * 4 + 3][row] = v.w;
        }
        __syncthreads();
        #pragma unroll
        for (int k = 0; k < BK; k++) {
            float a[TM], b[TN];
            #pragma unroll
            for (int m = 0; m < TM; m += 4)
                *(float4*)&a[m] = *(const float4*)&As[k][ty * TM + m];
            #pragma unroll
            for (int n = 0; n < TN; n += 4)
                *(float4*)&b[n] = *(const float4*)&Bs[k][tx * TN + n];
            #pragma unroll
            for (int m = 0; m < TM; m++)
                #pragma unroll
                for (int n = 0; n < TN; n++) acc[m][n] += a[m] * b[n];
        }
        __syncthreads();
    }

    #pragma unroll
    for (int m = 0; m < TM; m++) {
        int row = bm + ty * TM + m;
        #pragma unroll
        for (int n = 0; n < TN; n++) {
            int col = bn + tx * TN + n;
            float v = acc[m][n];
            if (ADDMAT) v += addm[(size_t)row * ldc + col];
            else        v += addv[col];
            if (TANH) v = tanhf(v);
            C[(size_t)row * ldc + col] = v;
        }
    }
}

__global__ void tanh_k(const float* __restrict__ in, float* __restrict__ out, int n) {
    int i = blockIdx.x * blockDim.x + threadIdx.x;
    if (i < n) out[i] = tanhf(in[i]);
}

// ---------------- Anderson update ----------------
struct AndArgs { const float* Z[6]; const float* F[6]; float* out; };

template<int MK>
__global__ void anderson_k(AndArgs a) {
    constexpr int PC = MK * (MK + 1) / 2 + MK;
    int tid = threadIdx.x;
    size_t idx = (size_t)blockIdx.x * DL + tid;
    float z[MK + 1], f[MK + 1];
    #pragma unroll
    for (int i = 0; i <= MK; i++) { z[i] = a.Z[i][idx]; f[i] = a.F[i][idx]; }
    float dF[MK], dG[MK];
    #pragma unroll
    for (int i = 0; i < MK; i++) {
        float dx = z[i] - z[i + 1];
        dF[i] = f[i] - f[i + 1];
        dG[i] = dF[i] - dx;
    }
    float r = f[0] - z[0];
    float part[PC];
    {
        int c = 0;
        #pragma unroll
        for (int i = 0; i < MK; i++)
            #pragma unroll
            for (int j = i; j < MK; j++) part[c++] = dG[i] * dG[j];
        #pragma unroll
        for (int i = 0; i < MK; i++) part[c++] = dG[i] * r;
    }
    __shared__ float s_part[8][PC];
    int lane = tid & 31, wid = tid >> 5;
    #pragma unroll
    for (int p = 0; p < PC; p++) {
        float v = part[p];
        #pragma unroll
        for (int o = 16; o; o >>= 1) v += __shfl_xor_sync(0xffffffffu, v, o);
        if (lane == 0) s_part[wid][p] = v;
    }
    __syncthreads();
    __shared__ float s_alpha[MK];
    if (tid == 0) {
        float S[PC];
        #pragma unroll
        for (int p = 0; p < PC; p++) {
            float s = 0.f;
            #pragma unroll
            for (int w = 0; w < 8; w++) s += s_part[w][p];
            S[p] = s;
        }
        float A[MK][MK], bv[MK];
        int cc = 0;
        for (int i = 0; i < MK; i++)
            for (int j = i; j < MK; j++) { A[i][j] = S[cc]; A[j][i] = S[cc]; cc++; }
        for (int i = 0; i < MK; i++) A[i][i] += 1e-4f;
        for (int i = 0; i < MK; i++) bv[i] = S[cc++];
        // Gaussian elimination (A is SPD + reg)
        for (int p = 0; p < MK; p++) {
            float ip = 1.f / A[p][p];
            for (int rr = p + 1; rr < MK; rr++) {
                float fc = A[rr][p] * ip;
                for (int q = p; q < MK; q++) A[rr][q] -= fc * A[p][q];
                bv[rr] -= fc * bv[p];
            }
        }
        for (int i = MK - 1; i >= 0; i--) {
            float s = bv[i];
            for (int j = i + 1; j < MK; j++) s -= A[i][j] * s_alpha[j];
            s_alpha[i] = s / A[i][i];
        }
    }
    __syncthreads();
    float o = f[0];
    #pragma unroll
    for (int i = 0; i < MK; i++) o -= dF[i] * s_alpha[i];
    a.out[idx] = o;
}

// ---------------- host orchestration ----------------
extern "C" void kernel_launch(void* const* d_in, const int* in_sizes, int n_in,
                              void* d_out, int out_size) {
    const float* ctx = (const float*)d_in[0];
    const float* W1  = (const float*)d_in[1];
    const float* b1  = (const float*)d_in[2];
    const float* W2  = (const float*)d_in[3];
    const float* b2  = (const float*)d_in[4];
    float* out = (float*)d_out;

    float *pW1s, *pW2s, *pu1, *pv1, *pu2, *pv2, *pP, *pH, *pX0, *pXs, *pFs;
    cudaGetSymbolAddress((void**)&pW1s, g_W1s);
    cudaGetSymbolAddress((void**)&pW2s, g_W2s);
    cudaGetSymbolAddress((void**)&pu1, g_u1);
    cudaGetSymbolAddress((void**)&pv1, g_v1);
    cudaGetSymbolAddress((void**)&pu2, g_u2);
    cudaGetSymbolAddress((void**)&pv2, g_v2);
    cudaGetSymbolAddress((void**)&pP,  g_P);
    cudaGetSymbolAddress((void**)&pH,  g_H);
    cudaGetSymbolAddress((void**)&pX0, g_X0);
    cudaGetSymbolAddress((void**)&pXs, g_Xs);
    cudaGetSymbolAddress((void**)&pFs, g_Fs);

    const size_t ZN = (size_t)NB * DL;

    // --- spectral normalization (20 power iterations, both matrices per launch) ---
    init_uv<<<4, 256>>>();
    MvP v1p{W1, HID, CIN, pu1, pv1}, v2p{W2, DL, HID, pu2, pv2};
    MvP u1p{W1, HID, CIN, pv1, pu1}, u2p{W2, DL, HID, pv2, pu2};
    for (int it = 0; it < 20; it++) {
        mv_vstep<<<dim3(4, 2), 256>>>(v1p, v2p);
        mv_ustep<<<dim3(4, 2), 256>>>(u1p, u2p);
    }
    mv_vstep<<<dim3(4, 2), 256>>>(v1p, v2p);  // final v = W^T u
    sigma_k<<<2, 256>>>();
    scale_k<<<(HID * CIN + DL * HID + 255) / 256, 256>>>(W1, W2);

    // --- loop-invariant context part: P = ctx @ W1c^T + b1 ---
    gemm_nt<128, 64, 16, 8, 4, false, false><<<dim3(HID / 64, NB / 128), 256>>>(
        ctx, XD, pW1s + 256, CIN, pP, HID, XD, b1, nullptr);

    auto Zp = [&](int t) -> float* {
        if (t == 0) return pX0;
        if (t <= 2) return pFs;                         // X[1]=X[2]=F0
        return pXs + (size_t)(t - 3) * ZN;
    };
    auto Fp = [&](int t) -> float* {
        if (t == 0) return pFs;
        if (t <= 2) return pFs + ZN;                    // F[2]=F[1] (duplicated warm-up)
        return pFs + (size_t)t * ZN;
    };

    auto feval = [&](const float* z, float* fo) {
        gemm_nt<128, 64, 16, 8, 4, true, true><<<dim3(HID / 64, NB / 128), 256>>>(
            z, DL, pW1s, CIN, pH, HID, DL, nullptr, pP);
        gemm_nt<64, 64, 16, 4, 4, true, false><<<dim3(DL / 64, NB / 64), 256>>>(
            pH, HID, pW2s, HID, fo, DL, HID, b2, nullptr);
    };

    // --- warm-up: t=0 (x0 = 0 -> H = tanh(P)), t=1; t=2 aliased ---
    cudaMemsetAsync(pX0, 0, ZN * sizeof(float), 0);
    tanh_k<<<(NB * HID + 255) / 256, 256>>>(pP, pH, NB * HID);
    gemm_nt<64, 64, 16, 4, 4, true, false><<<dim3(DL / 64, NB / 64), 256>>>(
        pH, HID, pW2s, HID, Fp(0), DL, HID, b2, nullptr);
    feval(Fp(0), Fp(1));

    // --- Anderson loop k = 2 .. 24 ---
    for (int k = 2; k < MAXIT; k++) {
        int mk = (k < 5) ? k : 5;
        AndArgs aa{};
        for (int i = 0; i <= mk; i++) { aa.Z[i] = Zp(k - i); aa.F[i] = Fp(k - i); }
        float* xo = (k == MAXIT - 1) ? out : Zp(k + 1);
        aa.out = xo;
        switch (mk) {
            case 2: anderson_k<2><<<NB, DL>>>(aa); break;
            case 3: anderson_k<3><<<NB, DL>>>(aa); break;
            case 4: anderson_k<4><<<NB, DL>>>(aa); break;
            default: anderson_k<5><<<NB, DL>>>(aa); break;
        }
        if (k < MAXIT - 1) feval(xo, Fp(k + 1));
    }
}

// round 4
// speedup vs baseline: 2.0822x; 2.0822x over previous
#include <cuda_runtime.h>
#include <math.h>
#include <stddef.h>

#define NB   2048
#define DL   256
#define XD   256
#define HID  1024
#define CIN  512
#define MAXIT 25

// ---------------- static device scratch (no allocs allowed) ----------------
__device__ float g_W1s[HID * CIN];
__device__ float g_W2s[DL * HID];
__device__ float g_u1[HID];
__device__ float g_v1[CIN];
__device__ float g_u2[DL];
__device__ float g_v2[HID];
__device__ float g_invsig[2];
__device__ float g_P[NB * HID];
__device__ float g_H[NB * HID];
__device__ float g_X0[NB * DL];
__device__ float g_Xs[23][NB * DL];   // X history slots t=3..25
__device__ float g_Fs[25][NB * DL];   // F history slots t=0..24

// ---------------- helpers ----------------
__device__ __forceinline__ float blk_reduce256(float v, float* sred, int tid) {
    #pragma unroll
    for (int o = 16; o; o >>= 1) v += __shfl_xor_sync(0xffffffffu, v, o);
    if ((tid & 31) == 0) sred[tid >> 5] = v;
    __syncthreads();
    if (tid < 32) {
        float x = (tid < 8) ? sred[tid] : 0.f;
        #pragma unroll
        for (int o = 4; o; o >>= 1) x += __shfl_xor_sync(0xffffffffu, x, o);
        if (tid == 0) sred[0] = x;
    }
    __syncthreads();
    float r = sred[0];
    __syncthreads();
    return r;
}

// ---------------- spectral norm power iteration ----------------
struct MvP { const float* W; int R; int C; const float* in; float* out; };

__global__ void init_uv() {
    int t = blockIdx.x * 256 + threadIdx.x;
    if (t < HID) g_u1[t] = 1.f;
    if (t < DL)  g_u2[t] = 1.f;
}

// out[C] = W^T normalize(in[R])   (output left UN-normalized; normalized on read)
// 32 columns per block, 8 row-group warps, cross-warp reduce in shared.
__global__ void mv_vstep(MvP pa, MvP pb) {
    MvP p = blockIdx.y ? pb : pa;
    int jbase = blockIdx.x * 32;
    if (jbase >= p.C) return;
    __shared__ float s_in[1024];
    __shared__ float sred[32];
    __shared__ float s_acc[8][33];
    int tid = threadIdx.x;
    float ss = 0.f;
    for (int i = tid; i < p.R; i += 256) { float v = p.in[i]; s_in[i] = v; ss += v * v; }
    ss = blk_reduce256(ss, sred, tid);
    float inv = 1.f / (sqrtf(ss) + 1e-12f);
    int lane = tid & 31, w = tid >> 5;
    const float* Wp = p.W + jbase + lane;
    float acc = 0.f;
    for (int i = w; i < p.R; i += 8)
        acc += Wp[(size_t)i * p.C] * s_in[i];
    s_acc[w][lane] = acc;
    __syncthreads();
    if (tid < 32) {
        float s = 0.f;
        #pragma unroll
        for (int w2 = 0; w2 < 8; w2++) s += s_acc[w2][tid];
        p.out[jbase + tid] = s * inv;
    }
}

// out[R] = W * normalize(in[C])
// warp-per-row (4 rows per warp), lane-strided coalesced loads + shuffle reduce.
__global__ void mv_ustep(MvP pa, MvP pb) {
    MvP p = blockIdx.y ? pb : pa;
    int rbase = blockIdx.x * 32;
    if (rbase >= p.R) return;
    __shared__ float s_in[1024];
    __shared__ float sred[32];
    int tid = threadIdx.x;
    float ss = 0.f;
    for (int j = tid; j < p.C; j += 256) { float v = p.in[j]; s_in[j] = v; ss += v * v; }
    ss = blk_reduce256(ss, sred, tid);
    float inv = 1.f / (sqrtf(ss) + 1e-12f);
    int lane = tid & 31, w = tid >> 5;
    #pragma unroll
    for (int rr = 0; rr < 4; rr++) {
        int i = rbase + w * 4 + rr;
        const float* Wr = p.W + (size_t)i * p.C;
        float acc = 0.f;
        for (int j = lane; j < p.C; j += 32) acc += Wr[j] * s_in[j];
        #pragma unroll
        for (int o = 16; o; o >>= 1) acc += __shfl_xor_sync(0xffffffffu, acc, o);
        if (lane == 0) p.out[i] = acc * inv;
    }
}

// sigma = ||v_raw||^2 / (||v_raw|| + 1e-12)   (== u . (W v_hat))
__global__ void sigma_k() {
    __shared__ float sred[32];
    const float* v = blockIdx.x ? g_v2 : g_v1;
    int n = blockIdx.x ? HID : CIN;
    int tid = threadIdx.x;
    float ss = 0.f;
    for (int i = tid; i < n; i += 256) { float x = v[i]; ss += x * x; }
    ss = blk_reduce256(ss, sred, tid);
    if (tid == 0) {
        float nr = sqrtf(ss);
        float sig = ss / (nr + 1e-12f);
        g_invsig[blockIdx.x] = 1.f / sig;
    }
}

__global__ void scale_k(const float* __restrict__ W1, const float* __restrict__ W2) {
    int i = blockIdx.x * 256 + threadIdx.x;
    const int n1 = HID * CIN;
    const int tot = n1 + DL * HID;
    if (i >= tot) return;
    if (i < n1) g_W1s[i] = W1[i] * g_invsig[0];
    else        g_W2s[i - n1] = W2[i - n1] * g_invsig[1];
}

// ---------------- GEMM (NT: both operands K-major) ----------------
// C[M,N] = act( A[M,K] @ B[N,K]^T + addend )
template<int BM, int BN, int BK, int TM, int TN, bool TANH, bool ADDMAT>
__global__ void __launch_bounds__((BM / TM) * (BN / TN))
gemm_nt(const float* __restrict__ A, int lda,
        const float* __restrict__ Bm, int ldb,
        float* __restrict__ C, int ldc, int K,
        const float* __restrict__ addv, const float* __restrict__ addm) {
    constexpr int THREADS = (BM / TM) * (BN / TN);
    constexpr int NX = BN / TN;
    __shared__ float As[BK][BM + 4];
    __shared__ float Bs[BK][BN + 4];
    int tid = threadIdx.x;
    int bm = blockIdx.y * BM, bn = blockIdx.x * BN;
    int tx = tid % NX, ty = tid / NX;
    float acc[TM][TN] = {};

    for (int k0 = 0; k0 < K; k0 += BK) {
        #pragma unroll
        for (int i = tid; i < BM * (BK / 4); i += THREADS) {
            int row = i / (BK / 4), c4 = i % (BK / 4);
            float4 v = *(const float4*)(A + (size_t)(bm + row) * lda + k0 + c4 * 4);
            As[c4 * 4 + 0][row] = v.x; As[c4 * 4 + 1][row] = v.y;
            As[c4 * 4 + 2][row] = v.z; As[c4 * 4 + 3][row] = v.w;
        }
        #pragma unroll
        for (int i = tid; i < BN * (BK / 4); i += THREADS) {
            int row = i / (BK / 4), c4 = i % (BK / 4);
            float4 v = *(const float4*)(Bm + (size_t)(bn + row) * ldb + k0 + c4 * 4);
            Bs[c4 * 4 + 0][row] = v.x; Bs[c4 * 4 + 1][row] = v.y;
            Bs[c4 * 4 + 2][row] = v.z; Bs[c4 * 4 + 3][row] = v.w;
        }
        __syncthreads();
        #pragma unroll
        for (int k = 0; k < BK; k++) {
            float a[TM], b[TN];
            #pragma unroll
            for (int m = 0; m < TM; m += 4)
                *(float4*)&a[m] = *(const float4*)&As[k][ty * TM + m];
            #pragma unroll
            for (int n = 0; n < TN; n += 4)
                *(float4*)&b[n] = *(const float4*)&Bs[k][tx * TN + n];
            #pragma unroll
            for (int m = 0; m < TM; m++)
                #pragma unroll
                for (int n = 0; n < TN; n++) acc[m][n] += a[m] * b[n];
        }
        __syncthreads();
    }

    #pragma unroll
    for (int m = 0; m < TM; m++) {
        int row = bm + ty * TM + m;
        #pragma unroll
        for (int n = 0; n < TN; n++) {
            int col = bn + tx * TN + n;
            float v = acc[m][n];
            if (ADDMAT) v += addm[(size_t)row * ldc + col];
            else        v += addv[col];
            if (TANH) v = tanhf(v);
            C[(size_t)row * ldc + col] = v;
        }
    }
}

__global__ void tanh_k(const float* __restrict__ in, float* __restrict__ out, int n) {
    int i = blockIdx.x * blockDim.x + threadIdx.x;
    if (i < n) out[i] = tanhf(in[i]);
}

// ---------------- Anderson update ----------------
struct AndArgs { const float* Z[6]; const float* F[6]; float* out; };

template<int MK>
__global__ void anderson_k(AndArgs a) {
    constexpr int PC = MK * (MK + 1) / 2 + MK;
    int tid = threadIdx.x;
    size_t idx = (size_t)blockIdx.x * DL + tid;
    float z[MK + 1], f[MK + 1];
    #pragma unroll
    for (int i = 0; i <= MK; i++) { z[i] = a.Z[i][idx]; f[i] = a.F[i][idx]; }
    float dF[MK], dG[MK];
    #pragma unroll
    for (int i = 0; i < MK; i++) {
        float dx = z[i] - z[i + 1];
        dF[i] = f[i] - f[i + 1];
        dG[i] = dF[i] - dx;
    }
    float r = f[0] - z[0];
    float part[PC];
    {
        int c = 0;
        #pragma unroll
        for (int i = 0; i < MK; i++)
            #pragma unroll
            for (int j = i; j < MK; j++) part[c++] = dG[i] * dG[j];
        #pragma unroll
        for (int i = 0; i < MK; i++) part[c++] = dG[i] * r;
    }
    __shared__ float s_part[8][PC];
    int lane = tid & 31, wid = tid >> 5;
    #pragma unroll
    for (int p = 0; p < PC; p++) {
        float v = part[p];
        #pragma unroll
        for (int o = 16; o; o >>= 1) v += __shfl_xor_sync(0xffffffffu, v, o);
        if (lane == 0) s_part[wid][p] = v;
    }
    __syncthreads();
    __shared__ float s_alpha[MK];
    if (tid == 0) {
        float S[PC];
        #pragma unroll
        for (int p = 0; p < PC; p++) {
            float s = 0.f;
            #pragma unroll
            for (int w = 0; w < 8; w++) s += s_part[w][p];
            S[p] = s;
        }
        float A[MK][MK], bv[MK];
        int cc = 0;
        for (int i = 0; i < MK; i++)
            for (int j = i; j < MK; j++) { A[i][j] = S[cc]; A[j][i] = S[cc]; cc++; }
        for (int i = 0; i < MK; i++) A[i][i] += 1e-4f;
        for (int i = 0; i < MK; i++) bv[i] = S[cc++];
        // Gaussian elimination (A is SPD + reg)
        for (int p = 0; p < MK; p++) {
            float ip = 1.f / A[p][p];
            for (int rr = p + 1; rr < MK; rr++) {
                float fc = A[rr][p] * ip;
                for (int q = p; q < MK; q++) A[rr][q] -= fc * A[p][q];
                bv[rr] -= fc * bv[p];
            }
        }
        for (int i = MK - 1; i >= 0; i--) {
            float s = bv[i];
            for (int j = i + 1; j < MK; j++) s -= A[i][j] * s_alpha[j];
            s_alpha[i] = s / A[i][i];
        }
    }
    __syncthreads();
    float o = f[0];
    #pragma unroll
    for (int i = 0; i < MK; i++) o -= dF[i] * s_alpha[i];
    a.out[idx] = o;
}

// ---------------- host orchestration ----------------
extern "C" void kernel_launch(void* const* d_in, const int* in_sizes, int n_in,
                              void* d_out, int out_size) {
    const float* ctx = (const float*)d_in[0];
    const float* W1  = (const float*)d_in[1];
    const float* b1  = (const float*)d_in[2];
    const float* W2  = (const float*)d_in[3];
    const float* b2  = (const float*)d_in[4];
    float* out = (float*)d_out;

    float *pW1s, *pW2s, *pu1, *pv1, *pu2, *pv2, *pP, *pH, *pX0, *pXs, *pFs;
    cudaGetSymbolAddress((void**)&pW1s, g_W1s);
    cudaGetSymbolAddress((void**)&pW2s, g_W2s);
    cudaGetSymbolAddress((void**)&pu1, g_u1);
    cudaGetSymbolAddress((void**)&pv1, g_v1);
    cudaGetSymbolAddress((void**)&pu2, g_u2);
    cudaGetSymbolAddress((void**)&pv2, g_v2);
    cudaGetSymbolAddress((void**)&pP,  g_P);
    cudaGetSymbolAddress((void**)&pH,  g_H);
    cudaGetSymbolAddress((void**)&pX0, g_X0);
    cudaGetSymbolAddress((void**)&pXs, g_Xs);
    cudaGetSymbolAddress((void**)&pFs, g_Fs);

    const size_t ZN = (size_t)NB * DL;

    // --- spectral normalization (20 power iterations, both matrices per launch) ---
    init_uv<<<4, 256>>>();
    MvP v1p{W1, HID, CIN, pu1, pv1}, v2p{W2, DL, HID, pu2, pv2};
    MvP u1p{W1, HID, CIN, pv1, pu1}, u2p{W2, DL, HID, pv2, pu2};
    for (int it = 0; it < 20; it++) {
        mv_vstep<<<dim3(32, 2), 256>>>(v1p, v2p);   // C/32 blocks used per matrix
        mv_ustep<<<dim3(32, 2), 256>>>(u1p, u2p);   // R/32 blocks used per matrix
    }
    mv_vstep<<<dim3(32, 2), 256>>>(v1p, v2p);  // final v = W^T u
    sigma_k<<<2, 256>>>();
    scale_k<<<(HID * CIN + DL * HID + 255) / 256, 256>>>(W1, W2);

    // --- loop-invariant context part: P = ctx @ W1c^T + b1 ---
    gemm_nt<128, 64, 16, 8, 4, false, false><<<dim3(HID / 64, NB / 128), 256>>>(
        ctx, XD, pW1s + 256, CIN, pP, HID, XD, b1, nullptr);

    auto Zp = [&](int t) -> float* {
        if (t == 0) return pX0;
        if (t <= 2) return pFs;                         // X[1]=X[2]=F0
        return pXs + (size_t)(t - 3) * ZN;
    };
    auto Fp = [&](int t) -> float* {
        if (t == 0) return pFs;
        if (t <= 2) return pFs + ZN;                    // F[2]=F[1] (duplicated warm-up)
        return pFs + (size_t)t * ZN;
    };

    auto feval = [&](const float* z, float* fo) {
        gemm_nt<128, 64, 16, 8, 4, true, true><<<dim3(HID / 64, NB / 128), 256>>>(
            z, DL, pW1s, CIN, pH, HID, DL, nullptr, pP);
        gemm_nt<64, 64, 16, 4, 4, true, false><<<dim3(DL / 64, NB / 64), 256>>>(
            pH, HID, pW2s, HID, fo, DL, HID, b2, nullptr);
    };

    // --- warm-up: t=0 (x0 = 0 -> H = tanh(P)), t=1; t=2 aliased ---
    cudaMemsetAsync(pX0, 0, ZN * sizeof(float), 0);
    tanh_k<<<(NB * HID + 255) / 256, 256>>>(pP, pH, NB * HID);
    gemm_nt<64, 64, 16, 4, 4, true, false><<<dim3(DL / 64, NB / 64), 256>>>(
        pH, HID, pW2s, HID, Fp(0), DL, HID, b2, nullptr);
    feval(Fp(0), Fp(1));

    // --- Anderson loop k = 2 .. 24 ---
    for (int k = 2; k < MAXIT; k++) {
        int mk = (k < 5) ? k : 5;
        AndArgs aa{};
        for (int i = 0; i <= mk; i++) { aa.Z[i] = Zp(k - i); aa.F[i] = Fp(k - i); }
        float* xo = (k == MAXIT - 1) ? out : Zp(k + 1);
        aa.out = xo;
        switch (mk) {
            case 2: anderson_k<2><<<NB, DL>>>(aa); break;
            case 3: anderson_k<3><<<NB, DL>>>(aa); break;
            case 4: anderson_k<4><<<NB, DL>>>(aa); break;
            default: anderson_k<5><<<NB, DL>>>(aa); break;
        }
        if (k < MAXIT - 1) feval(xo, Fp(k + 1));
    }
}

// round 5
// speedup vs baseline: 2.1297x; 1.0228x over previous
#include <cuda_runtime.h>
#include <math.h>
#include <stddef.h>

#define NB   2048
#define DL   256
#define XD   256
#define HID  1024
#define CIN  512
#define MAXIT 25
#define SPEC_GRP 32

// ---------------- static device scratch (no allocs allowed) ----------------
__device__ float g_W1s[HID * CIN];
__device__ float g_W2s[DL * HID];
__device__ float g_u1[HID];
__device__ float g_v1[CIN];
__device__ float g_u2[DL];
__device__ float g_v2[HID];
__device__ float g_invsig[2];
__device__ float g_P[NB * HID];
__device__ float g_H[NB * HID];
__device__ float g_X0[NB * DL];
__device__ float g_Xs[23][NB * DL];   // X history slots t=3..25
__device__ float g_Fs[25][NB * DL];   // F history slots t=0..24

__device__ unsigned g_bar_cnt[2]   = {0u, 0u};
__device__ unsigned g_bar_epoch[2] = {0u, 0u};

// ---------------- helpers ----------------
__device__ __forceinline__ float blk_reduce256(float v, float* sred, int tid) {
    #pragma unroll
    for (int o = 16; o; o >>= 1) v += __shfl_xor_sync(0xffffffffu, v, o);
    if ((tid & 31) == 0) sred[tid >> 5] = v;
    __syncthreads();
    if (tid < 32) {
        float x = (tid < 8) ? sred[tid] : 0.f;
        #pragma unroll
        for (int o = 4; o; o >>= 1) x += __shfl_xor_sync(0xffffffffu, x, o);
        if (tid == 0) sred[0] = x;
    }
    __syncthreads();
    float r = sred[0];
    __syncthreads();
    return r;
}

// per-group software grid barrier (32 blocks per group, all co-resident)
__device__ __forceinline__ void grid_bar(int g, int tid) {
    __syncthreads();
    if (tid == 0) {
        volatile unsigned* ep = (volatile unsigned*)&g_bar_epoch[g];
        unsigned e = *ep;
        __threadfence();
        unsigned old = atomicAdd(&g_bar_cnt[g], 1u);
        if (old == SPEC_GRP - 1) {
            g_bar_cnt[g] = 0;
            __threadfence();
            *ep = e + 1;
        } else {
            while (*ep == e) __nanosleep(40);
        }
        __threadfence();
    }
    __syncthreads();
}

// ---------------- fused spectral-norm power iteration ----------------
// vstep: out[C] = W^T normalize(in[R])   (output left UN-normalized)
template<int R, int C>
__device__ void vstep_t(const float* __restrict__ W, const float* __restrict__ in,
                        float* __restrict__ out, int blk, int tid) {
    __shared__ float s_in[1024];
    __shared__ float sred[32];
    __shared__ float s_acc[8][33];
    float ss = 0.f;
    for (int i = tid; i < R; i += 256) { float v = __ldcg(in + i); s_in[i] = v; ss += v * v; }
    ss = blk_reduce256(ss, sred, tid);
    float inv = 1.f / (sqrtf(ss) + 1e-12f);
    int lane = tid & 31, w = tid >> 5;
    for (int t = blk; t < C / 32; t += SPEC_GRP) {
        const float* Wp = W + t * 32 + lane;
        float acc = 0.f;
        #pragma unroll 8
        for (int i = w; i < R; i += 8)
            acc += Wp[(size_t)i * C] * s_in[i];
        s_acc[w][lane] = acc;
        __syncthreads();
        if (tid < 32) {
            float s = 0.f;
            #pragma unroll
            for (int w2 = 0; w2 < 8; w2++) s += s_acc[w2][tid];
            out[t * 32 + tid] = s * inv;
        }
        __syncthreads();
    }
}

// ustep: out[R] = W * normalize(in[C])
template<int R, int C>
__device__ void ustep_t(const float* __restrict__ W, const float* __restrict__ in,
                        float* __restrict__ out, int blk, int tid) {
    __shared__ float s_in2[1024];
    __shared__ float sred2[32];
    float ss = 0.f;
    for (int j = tid; j < C; j += 256) { float v = __ldcg(in + j); s_in2[j] = v; ss += v * v; }
    ss = blk_reduce256(ss, sred2, tid);
    float inv = 1.f / (sqrtf(ss) + 1e-12f);
    int lane = tid & 31, w = tid >> 5;
    for (int t = blk; t < R / 32; t += SPEC_GRP) {
        #pragma unroll
        for (int rr = 0; rr < 4; rr++) {
            int i = t * 32 + w * 4 + rr;
            const float* Wr = W + (size_t)i * C;
            float acc = 0.f;
            #pragma unroll 8
            for (int j = lane; j < C; j += 32) acc += Wr[j] * s_in2[j];
            #pragma unroll
            for (int o = 16; o; o >>= 1) acc += __shfl_xor_sync(0xffffffffu, acc, o);
            if (lane == 0) out[i] = acc * inv;
        }
    }
}

template<int R, int C>
__device__ void spec_group(const float* __restrict__ W, float* u, float* v,
                           int g, int blk, int tid) {
    // u = ones (redundant writes, same value)
    for (int i = tid; i < R; i += 256) u[i] = 1.f;
    grid_bar(g, tid);
    for (int it = 0; it < 20; it++) {
        vstep_t<R, C>(W, u, v, blk, tid);
        grid_bar(g, tid);
        ustep_t<R, C>(W, v, u, blk, tid);
        grid_bar(g, tid);
    }
    vstep_t<R, C>(W, u, v, blk, tid);     // final v = W^T u (unnormalized)
    grid_bar(g, tid);
    if (blk == 0) {
        __shared__ float sred3[32];
        float ss = 0.f;
        for (int i = tid; i < C; i += 256) { float x = __ldcg(v + i); ss += x * x; }
        ss = blk_reduce256(ss, sred3, tid);
        if (tid == 0) {
            float nr = sqrtf(ss);
            float sig = ss / (nr + 1e-12f);   // == u . (W v_hat)
            g_invsig[g] = 1.f / sig;
        }
    }
}

__global__ void __launch_bounds__(256) spec_kernel(const float* __restrict__ W1,
                                                   const float* __restrict__ W2) {
    int tid = threadIdx.x;
    int g = (blockIdx.x >= SPEC_GRP) ? 1 : 0;
    int blk = blockIdx.x - g * SPEC_GRP;
    if (g == 0) spec_group<HID, CIN>(W1, g_u1, g_v1, 0, blk, tid);
    else        spec_group<DL, HID>(W2, g_u2, g_v2, 1, blk, tid);
}

__global__ void scale_k(const float* __restrict__ W1, const float* __restrict__ W2) {
    int i = blockIdx.x * 256 + threadIdx.x;
    const int n1 = HID * CIN;
    const int tot = n1 + DL * HID;
    if (i >= tot) return;
    if (i < n1) g_W1s[i] = W1[i] * g_invsig[0];
    else        g_W2s[i - n1] = W2[i - n1] * g_invsig[1];
}

// ---------------- GEMM (NT: both operands K-major) ----------------
// C[M,N] = act( A[M,K] @ B[N,K]^T + addend )
template<int BM, int BN, int BK, int TM, int TN, bool TANH, bool ADDMAT>
__global__ void __launch_bounds__((BM / TM) * (BN / TN))
gemm_nt(const float* __restrict__ A, int lda,
        const float* __restrict__ Bm, int ldb,
        float* __restrict__ C, int ldc, int K,
        const float* __restrict__ addv, const float* __restrict__ addm) {
    constexpr int THREADS = (BM / TM) * (BN / TN);
    constexpr int NX = BN / TN;
    __shared__ float As[BK][BM + 4];
    __shared__ float Bs[BK][BN + 4];
    int tid = threadIdx.x;
    int bm = blockIdx.y * BM, bn = blockIdx.x * BN;
    int tx = tid % NX, ty = tid / NX;
    float acc[TM][TN] = {};

    for (int k0 = 0; k0 < K; k0 += BK) {
        #pragma unroll
        for (int i = tid; i < BM * (BK / 4); i += THREADS) {
            int row = i / (BK / 4), c4 = i % (BK / 4);
            float4 v = *(const float4*)(A + (size_t)(bm + row) * lda + k0 + c4 * 4);
            As[c4 * 4 + 0][row] = v.x; As[c4 * 4 + 1][row] = v.y;
            As[c4 * 4 + 2][row] = v.z; As[c4 * 4 + 3][row] = v.w;
        }
        #pragma unroll
        for (int i = tid; i < BN * (BK / 4); i += THREADS) {
            int row = i / (BK / 4), c4 = i % (BK / 4);
            float4 v = *(const float4*)(Bm + (size_t)(bn + row) * ldb + k0 + c4 * 4);
            Bs[c4 * 4 + 0][row] = v.x; Bs[c4 * 4 + 1][row] = v.y;
            Bs[c4 * 4 + 2][row] = v.z; Bs[c4 * 4 + 3][row] = v.w;
        }
        __syncthreads();
        #pragma unroll
        for (int k = 0; k < BK; k++) {
            float a[TM], b[TN];
            #pragma unroll
            for (int m = 0; m < TM; m += 4)
                *(float4*)&a[m] = *(const float4*)&As[k][ty * TM + m];
            #pragma unroll
            for (int n = 0; n < TN; n += 4)
                *(float4*)&b[n] = *(const float4*)&Bs[k][tx * TN + n];
            #pragma unroll
            for (int m = 0; m < TM; m++)
                #pragma unroll
                for (int n = 0; n < TN; n++) acc[m][n] += a[m] * b[n];
        }
        __syncthreads();
    }

    #pragma unroll
    for (int m = 0; m < TM; m++) {
        int row = bm + ty * TM + m;
        #pragma unroll
        for (int n = 0; n < TN; n++) {
            int col = bn + tx * TN + n;
            float v = acc[m][n];
            if (ADDMAT) v += addm[(size_t)row * ldc + col];
            else        v += addv[col];
            if (TANH) v = tanhf(v);
            C[(size_t)row * ldc + col] = v;
        }
    }
}

__global__ void tanh_k(const float* __restrict__ in, float* __restrict__ out, int n) {
    int i = blockIdx.x * blockDim.x + threadIdx.x;
    if (i < n) out[i] = tanhf(in[i]);
}

// ---------------- Anderson update ----------------
struct AndArgs { const float* Z[6]; const float* F[6]; float* out; };

template<int MK>
__global__ void anderson_k(AndArgs a) {
    constexpr int PC = MK * (MK + 1) / 2 + MK;
    int tid = threadIdx.x;
    size_t idx = (size_t)blockIdx.x * DL + tid;
    float z[MK + 1], f[MK + 1];
    #pragma unroll
    for (int i = 0; i <= MK; i++) { z[i] = a.Z[i][idx]; f[i] = a.F[i][idx]; }
    float dF[MK], dG[MK];
    #pragma unroll
    for (int i = 0; i < MK; i++) {
        float dx = z[i] - z[i + 1];
        dF[i] = f[i] - f[i + 1];
        dG[i] = dF[i] - dx;
    }
    float r = f[0] - z[0];
    float part[PC];
    {
        int c = 0;
        #pragma unroll
        for (int i = 0; i < MK; i++)
            #pragma unroll
            for (int j = i; j < MK; j++) part[c++] = dG[i] * dG[j];
        #pragma unroll
        for (int i = 0; i < MK; i++) part[c++] = dG[i] * r;
    }
    __shared__ float s_part[8][PC];
    int lane = tid & 31, wid = tid >> 5;
    #pragma unroll
    for (int p = 0; p < PC; p++) {
        float v = part[p];
        #pragma unroll
        for (int o = 16; o; o >>= 1) v += __shfl_xor_sync(0xffffffffu, v, o);
        if (lane == 0) s_part[wid][p] = v;
    }
    __syncthreads();
    __shared__ float s_alpha[MK];
    if (tid == 0) {
        float S[PC];
        #pragma unroll
        for (int p = 0; p < PC; p++) {
            float s = 0.f;
            #pragma unroll
            for (int w = 0; w < 8; w++) s += s_part[w][p];
            S[p] = s;
        }
        float A[MK][MK], bv[MK];
        int cc = 0;
        for (int i = 0; i < MK; i++)
            for (int j = i; j < MK; j++) { A[i][j] = S[cc]; A[j][i] = S[cc]; cc++; }
        for (int i = 0; i < MK; i++) A[i][i] += 1e-4f;
        for (int i = 0; i < MK; i++) bv[i] = S[cc++];
        // Gaussian elimination (A is SPD + reg)
        for (int p = 0; p < MK; p++) {
            float ip = 1.f / A[p][p];
            for (int rr = p + 1; rr < MK; rr++) {
                float fc = A[rr][p] * ip;
                for (int q = p; q < MK; q++) A[rr][q] -= fc * A[p][q];
                bv[rr] -= fc * bv[p];
            }
        }
        for (int i = MK - 1; i >= 0; i--) {
            float s = bv[i];
            for (int j = i + 1; j < MK; j++) s -= A[i][j] * s_alpha[j];
            s_alpha[i] = s / A[i][i];
        }
    }
    __syncthreads();
    float o = f[0];
    #pragma unroll
    for (int i = 0; i < MK; i++) o -= dF[i] * s_alpha[i];
    a.out[idx] = o;
}

// ---------------- host orchestration ----------------
extern "C" void kernel_launch(void* const* d_in, const int* in_sizes, int n_in,
                              void* d_out, int out_size) {
    const float* ctx = (const float*)d_in[0];
    const float* W1  = (const float*)d_in[1];
    const float* b1  = (const float*)d_in[2];
    const float* W2  = (const float*)d_in[3];
    const float* b2  = (const float*)d_in[4];
    float* out = (float*)d_out;

    float *pW1s, *pW2s, *pP, *pH, *pX0, *pXs, *pFs;
    cudaGetSymbolAddress((void**)&pW1s, g_W1s);
    cudaGetSymbolAddress((void**)&pW2s, g_W2s);
    cudaGetSymbolAddress((void**)&pP,  g_P);
    cudaGetSymbolAddress((void**)&pH,  g_H);
    cudaGetSymbolAddress((void**)&pX0, g_X0);
    cudaGetSymbolAddress((void**)&pXs, g_Xs);
    cudaGetSymbolAddress((void**)&pFs, g_Fs);

    const size_t ZN = (size_t)NB * DL;

    // --- spectral normalization: ONE persistent kernel (both matrices) ---
    spec_kernel<<<2 * SPEC_GRP, 256>>>(W1, W2);
    scale_k<<<(HID * CIN + DL * HID + 255) / 256, 256>>>(W1, W2);

    // --- loop-invariant context part: P = ctx @ W1c^T + b1 ---
    gemm_nt<128, 64, 16, 8, 4, false, false><<<dim3(HID / 64, NB / 128), 256>>>(
        ctx, XD, pW1s + 256, CIN, pP, HID, XD, b1, nullptr);

    auto Zp = [&](int t) -> float* {
        if (t == 0) return pX0;
        if (t <= 2) return pFs;                         // X[1]=X[2]=F0
        return pXs + (size_t)(t - 3) * ZN;
    };
    auto Fp = [&](int t) -> float* {
        if (t == 0) return pFs;
        if (t <= 2) return pFs + ZN;                    // F[2]=F[1] (duplicated warm-up)
        return pFs + (size_t)t * ZN;
    };

    auto feval = [&](const float* z, float* fo) {
        gemm_nt<128, 64, 16, 8, 4, true, true><<<dim3(HID / 64, NB / 128), 256>>>(
            z, DL, pW1s, CIN, pH, HID, DL, nullptr, pP);
        gemm_nt<64, 64, 16, 4, 4, true, false><<<dim3(DL / 64, NB / 64), 256>>>(
            pH, HID, pW2s, HID, fo, DL, HID, b2, nullptr);
    };

    // --- warm-up: t=0 (x0 = 0 -> H = tanh(P)), t=1; t=2 aliased ---
    cudaMemsetAsync(pX0, 0, ZN * sizeof(float), 0);
    tanh_k<<<(NB * HID + 255) / 256, 256>>>(pP, pH, NB * HID);
    gemm_nt<64, 64, 16, 4, 4, true, false><<<dim3(DL / 64, NB / 64), 256>>>(
        pH, HID, pW2s, HID, Fp(0), DL, HID, b2, nullptr);
    feval(Fp(0), Fp(1));

    // --- Anderson loop k = 2 .. 24 ---
    for (int k = 2; k < MAXIT; k++) {
        int mk = (k < 5) ? k : 5;
        AndArgs aa{};
        for (int i = 0; i <= mk; i++) { aa.Z[i] = Zp(k - i); aa.F[i] = Fp(k - i); }
        float* xo = (k == MAXIT - 1) ? out : Zp(k + 1);
        aa.out = xo;
        switch (mk) {
            case 2: anderson_k<2><<<NB, DL>>>(aa); break;
            case 3: anderson_k<3><<<NB, DL>>>(aa); break;
            case 4: anderson_k<4><<<NB, DL>>>(aa); break;
            default: anderson_k<5><<<NB, DL>>>(aa); break;
        }
        if (k < MAXIT - 1) feval(xo, Fp(k + 1));
    }
}